// round 17
// baseline (speedup 1.0000x reference)
#include <cuda_runtime.h>
#include <cuda_bf16.h>
#include <math.h>
#include <cstdint>

typedef __nv_bfloat16 bf16;

// ---------------- problem constants ----------------
#define Bb   2
#define Lq   1024
#define Vn   1024
#define Hh   4096
#define NHh  32
#define HDd  128
#define Mrows (Bb*Lq)          // 2048
#define QSCALE 0.08838834764831845f   // 1/sqrt(128)

#define A4n ((long long)Mrows*Hh/4)   // 2M float4
#define W4n ((long long)Hh*Hh/4)      // 4M float4

// ---------------- scratch (device globals) ----------------------------------
__device__ bf16  g_hb [(size_t)Mrows*Hh];
__device__ bf16  g_vb [(size_t)Mrows*Hh];
__device__ bf16  g_Wqb[(size_t)Hh*Hh];
__device__ bf16  g_Wkb[(size_t)Hh*Hh];
__device__ bf16  g_Wvb[(size_t)Hh*Hh];
__device__ bf16  g_Wob[(size_t)Hh*Hh];
__device__ bf16  g_Qb [(size_t)Mrows*Hh];
__device__ bf16  g_Kb [(size_t)Mrows*Hh];
__device__ bf16  g_Vb [(size_t)Mrows*Hh];
__device__ bf16  g_ctx[(size_t)Mrows*Hh];
__device__ float g_X  [(size_t)Mrows*Hh];

// ---------------- low-level helpers -----------------------------------------
__device__ __forceinline__ void cpasync16(void* sdst, const void* gsrc) {
    unsigned s = (unsigned)__cvta_generic_to_shared(sdst);
    asm volatile("cp.async.cg.shared.global [%0], [%1], 16;" :: "r"(s), "l"(gsrc));
}
__device__ __forceinline__ void cp_commit() { asm volatile("cp.async.commit_group;"); }
__device__ __forceinline__ void cp_wait0()  { asm volatile("cp.async.wait_group 0;"); }

__device__ __forceinline__ void ldsm4(uint32_t& r0, uint32_t& r1, uint32_t& r2, uint32_t& r3,
                                      const void* p) {
    unsigned a = (unsigned)__cvta_generic_to_shared(p);
    asm volatile("ldmatrix.sync.aligned.m8n8.x4.shared.b16 {%0,%1,%2,%3}, [%4];"
                 : "=r"(r0), "=r"(r1), "=r"(r2), "=r"(r3) : "r"(a));
}
__device__ __forceinline__ void ldsm4t(uint32_t& r0, uint32_t& r1, uint32_t& r2, uint32_t& r3,
                                       const void* p) {
    unsigned a = (unsigned)__cvta_generic_to_shared(p);
    asm volatile("ldmatrix.sync.aligned.m8n8.x4.trans.shared.b16 {%0,%1,%2,%3}, [%4];"
                 : "=r"(r0), "=r"(r1), "=r"(r2), "=r"(r3) : "r"(a));
}

__device__ __forceinline__ void mma16816(float* c, const uint32_t* a, const uint32_t* b) {
    asm volatile(
        "mma.sync.aligned.m16n8k16.row.col.f32.bf16.bf16.f32 "
        "{%0,%1,%2,%3}, {%4,%5,%6,%7}, {%8,%9}, {%0,%1,%2,%3};"
        : "+f"(c[0]), "+f"(c[1]), "+f"(c[2]), "+f"(c[3])
        : "r"(a[0]), "r"(a[1]), "r"(a[2]), "r"(a[3]), "r"(b[0]), "r"(b[1]));
}

__device__ __forceinline__ void cvt_one(const float4* s, uint2* d, size_t i) {
    float4 x = s[i];
    __nv_bfloat162 a = __floats2bfloat162_rn(x.x, x.y);
    __nv_bfloat162 b = __floats2bfloat162_rn(x.z, x.w);
    uint2 p; p.x = *(unsigned*)&a; p.y = *(unsigned*)&b;
    d[i] = p;
}

// ============================================================================
// standalone fp32 -> bf16 conversion for up to two tensors
// ============================================================================
__global__ __launch_bounds__(256) void f2bf2(
    const float* __restrict__ s0, bf16* __restrict__ d0, long long n0,
    const float* __restrict__ s1, bf16* __restrict__ d1, long long n1)
{
    long long i = ((long long)blockIdx.x * 256 + threadIdx.x) * 2;
    #pragma unroll
    for (int u = 0; u < 2; u++) {
        long long j = i + u;
        if (j < n0)            cvt_one((const float4*)s0, (uint2*)d0, (size_t)j);
        else if (j - n0 < n1)  cvt_one((const float4*)s1, (uint2*)d1, (size_t)(j - n0));
    }
}

// ============================================================================
// mma.sync bf16 GEMM: out = (A[M,K] @ W[N,K]^T + bias) * scale (+resid)
// CTA tile 128x128, BK=64, NST=3 cp.async stages, 4 warps (2x2), warp 64x64.
// 128 threads/CTA, ~254 regs -> 2 CTAs/SM (221KB smem): dual-CTA latency hiding.
// Flat k16 pipeline with cross-chunk fragment prefetch.
// Extra blocks (blockIdx.y >= 16) run fp32->bf16 conversion for the NEXT
// launch's operands, filling wave-tail idle SMs.
// ============================================================================
#define TBM 128
#define TBN 128
#define TKC 64
#define NST 3
#define LDT 72
#define STG_HALVES ((TBM+TBN)*LDT)              // 18432 halves = 36864 B
#define GEMM_SMEM (NST*STG_HALVES*2)            // 110592 bytes
#define NKI (Hh / TKC)                          // 64
#define GT 128                                  // gemm threads
#define CONV_ROWS 10                            // 10*32 = 320 conv blocks

__device__ __forceinline__ void load_stage(bf16* smb, const bf16* Ab, const bf16* Wb,
                                           int slot, int k0, int tid)
{
    bf16* Sa = smb + (size_t)slot * STG_HALVES;
    bf16* Sb = Sa + TBM * LDT;
    #pragma unroll
    for (int i = 0; i < 8; i++) {               // A: 128 rows x 8 chunks = 1024
        int ch = tid + i * GT, r = ch >> 3, c = ch & 7;
        cpasync16(Sa + r * LDT + c * 8, Ab + (size_t)r * Hh + k0 + c * 8);
    }
    #pragma unroll
    for (int i = 0; i < 8; i++) {               // B: 128 rows x 8 chunks = 1024
        int ch = tid + i * GT, r = ch >> 3, c = ch & 7;
        cpasync16(Sb + r * LDT + c * 8, Wb + (size_t)r * Hh + k0 + c * 8);
    }
    cp_commit();
}

__global__ __launch_bounds__(GT) void gemm_mma(
    const bf16* __restrict__ A, const bf16* __restrict__ W,
    const float* __restrict__ bias, const float* __restrict__ resid,
    void* __restrict__ outv, float scale, int mode,
    const float* __restrict__ csrc0, bf16* __restrict__ cdst0, long long cn0,
    const float* __restrict__ csrc1, bf16* __restrict__ cdst1, long long cn1)
{
    const int tid = threadIdx.x;

    // ---- conversion blocks (fill wave-tail idle SMs) ----
    if (blockIdx.y >= 16) {
        const int c = (blockIdx.y - 16) * gridDim.x + blockIdx.x;
        const long long CB = (long long)(gridDim.y - 16) * gridDim.x;
        const long long stride = CB * GT;
        if (csrc0)
            for (long long i = (long long)c * GT + tid; i < cn0; i += stride)
                cvt_one((const float4*)csrc0, (uint2*)cdst0, (size_t)i);
        if (csrc1)
            for (long long i = (long long)c * GT + tid; i < cn1; i += stride)
                cvt_one((const float4*)csrc1, (uint2*)cdst1, (size_t)i);
        return;
    }

    extern __shared__ bf16 smb[];
    const int warp = tid >> 5, lane = tid & 31;
    const int wm = warp >> 1;                   // 0..1 -> 64 rows
    const int wn = warp & 1;                    // 0..1 -> 64 cols
    const int bn = blockIdx.x, bm = blockIdx.y;

    const bf16* Ab = A + (size_t)(bm * TBM) * Hh;
    const bf16* Wb = W + (size_t)(bn * TBN) * Hh;

    float acc[4][8][4];
    #pragma unroll
    for (int i = 0; i < 4; i++)
        #pragma unroll
        for (int j = 0; j < 8; j++)
            #pragma unroll
            for (int e = 0; e < 4; e++) acc[i][j][e] = 0.0f;

    load_stage(smb, Ab, Wb, 0, 0, tid);
    load_stage(smb, Ab, Wb, 1, TKC, tid);

    const int a_row = (lane & 15);
    const int a_kof = (lane >> 4) * 8;
    const int b_row = (lane & 7) + ((lane >> 4) * 8);
    const int b_kof = ((lane >> 3) & 1) * 8;

    uint32_t af[2][4][4];
    uint32_t bfr[2][8][2];

    #pragma unroll 1
    for (int kt = 0; kt < NKI; kt++) {
        cp_wait0();              // stages kt and kt+1 resident
        __syncthreads();         // all warps done reading stage kt-1 (slot of kt+2)
        if (kt + 2 < NKI)
            load_stage(smb, Ab, Wb, (kt + 2) % NST, (kt + 2) * TKC, tid);

        const bf16* Sa = smb + (size_t)(kt % NST) * STG_HALVES;
        const bf16* Sb = Sa + TBM * LDT;

        if (kt == 0) {           // one-time prime of buffer 0
            #pragma unroll
            for (int i = 0; i < 4; i++)
                ldsm4(af[0][i][0], af[0][i][1], af[0][i][2], af[0][i][3],
                      Sa + (wm*64 + i*16 + a_row) * LDT + a_kof);
            #pragma unroll
            for (int j = 0; j < 4; j++) {
                uint32_t r0, r1, r2, r3;
                ldsm4(r0, r1, r2, r3,
                      Sb + (wn*64 + j*16 + b_row) * LDT + b_kof);
                bfr[0][j*2  ][0] = r0; bfr[0][j*2  ][1] = r1;
                bfr[0][j*2+1][0] = r2; bfr[0][j*2+1][1] = r3;
            }
        }

        #pragma unroll
        for (int s = 0; s < TKC / 16; s++) {
            const int cb = s & 1, nb = cb ^ 1;
            if (s < 3) {
                const int ks = (s + 1) * 16;
                #pragma unroll
                for (int i = 0; i < 4; i++)
                    ldsm4(af[nb][i][0], af[nb][i][1], af[nb][i][2], af[nb][i][3],
                          Sa + (wm*64 + i*16 + a_row) * LDT + ks + a_kof);
                #pragma unroll
                for (int j = 0; j < 4; j++) {
                    uint32_t r0, r1, r2, r3;
                    ldsm4(r0, r1, r2, r3,
                          Sb + (wn*64 + j*16 + b_row) * LDT + ks + b_kof);
                    bfr[nb][j*2  ][0] = r0; bfr[nb][j*2  ][1] = r1;
                    bfr[nb][j*2+1][0] = r2; bfr[nb][j*2+1][1] = r3;
                }
            } else if (kt + 1 < NKI) {
                const bf16* Na = smb + (size_t)((kt + 1) % NST) * STG_HALVES;
                const bf16* Nb = Na + TBM * LDT;
                #pragma unroll
                for (int i = 0; i < 4; i++)
                    ldsm4(af[nb][i][0], af[nb][i][1], af[nb][i][2], af[nb][i][3],
                          Na + (wm*64 + i*16 + a_row) * LDT + a_kof);
                #pragma unroll
                for (int j = 0; j < 4; j++) {
                    uint32_t r0, r1, r2, r3;
                    ldsm4(r0, r1, r2, r3,
                          Nb + (wn*64 + j*16 + b_row) * LDT + b_kof);
                    bfr[nb][j*2  ][0] = r0; bfr[nb][j*2  ][1] = r1;
                    bfr[nb][j*2+1][0] = r2; bfr[nb][j*2+1][1] = r3;
                }
            }
            #pragma unroll
            for (int i = 0; i < 4; i++)
                #pragma unroll
                for (int j = 0; j < 8; j++)
                    mma16816(acc[i][j], af[cb][i], bfr[cb][j]);
        }
    }

    // ---- register epilogue ----
    bf16*  outb = (bf16*)outv;
    float* outf = (float*)outv;
    const int mbase = bm * TBM + wm * 64 + (lane >> 2);
    const int nbase = bn * TBN + wn * 64 + (lane & 3) * 2;
    #pragma unroll
    for (int i = 0; i < 4; i++) {
        #pragma unroll
        for (int j = 0; j < 8; j++) {
            const int n = nbase + j * 8;
            const float b0 = bias[n], b1 = bias[n + 1];
            #pragma unroll
            for (int half = 0; half < 2; half++) {
                const int m = mbase + i * 16 + half * 8;
                float v0 = (acc[i][j][half*2]     + b0) * scale;
                float v1 = (acc[i][j][half*2 + 1] + b1) * scale;
                if (mode == 0) {
                    __nv_bfloat162 p = __floats2bfloat162_rn(v0, v1);
                    *(__nv_bfloat162*)(outb + (size_t)m * Hh + n) = p;
                } else {
                    const float* rp = resid + (size_t)m * Hh + n;
                    float2 o; o.x = v0 + rp[0]; o.y = v1 + rp[1];
                    *(float2*)(outf + (size_t)m * Hh + n) = o;
                }
            }
        }
    }
}

// ============================================================================
// Flash cross-attention v3 — unchanged
// ============================================================================
#define LDK 136
#define LDP2 72
#define ATTN3_SMEM ((64*LDK + 2*2*64*LDK + 64*LDP2)*2 + 3*128*4)   // 97792

__global__ __launch_bounds__(256, 2) void attn3(
    const bf16* __restrict__ Q, const bf16* __restrict__ K,
    const bf16* __restrict__ V, const int* __restrict__ amask,
    bf16* __restrict__ ctx)
{
    extern __shared__ char smr[];
    bf16*  Qs  = (bf16*)smr;
    bf16*  KVs = Qs + 64*LDK;
    bf16*  Ps  = KVs + 2*2*64*LDK;
    float* pm    = (float*)(Ps + 64*LDP2);
    float* psum  = pm + 128;
    float* sbias = psum + 128;

    const int tid = threadIdx.x, warp = tid >> 5, lane = tid & 31;
    const int wm = warp >> 1;
    const int wn = warp & 1;
    const int b = blockIdx.y >> 5, h = blockIdx.y & 31;
    const int lt = blockIdx.x;

    const int r0 = lane >> 2;
    const int qp = lane & 3;
    const int a_row = lane & 15;
    const int a_kof = (lane >> 4) * 8;
    const int b_row = (lane & 7) + ((lane >> 4) * 8);
    const int b_kof = ((lane >> 3) & 1) * 8;

    const bf16* Qb = Q + ((size_t)(b*Lq + lt*64)) * Hh + h*HDd;
    #pragma unroll
    for (int e = tid; e < 64*16; e += 256) {
        int r = e >> 4, c = (e & 15) * 8;
        *(uint4*)(Qs + r*LDK + c) = *(const uint4*)(Qb + (size_t)r*Hh + c);
    }
    {
        bf16* Ks0 = KVs;
        bf16* Vs0 = KVs + 64*LDK;
        const bf16* Kb = K + ((size_t)(b*Vn)) * Hh + h*HDd;
        const bf16* Vb = V + ((size_t)(b*Vn)) * Hh + h*HDd;
        #pragma unroll
        for (int i = 0; i < 4; i++) {
            int ch = tid + i * 256, r = ch >> 4, c = (ch & 15) * 8;
            cpasync16(Ks0 + r*LDK + c, Kb + (size_t)r*Hh + c);
        }
        #pragma unroll
        for (int i = 0; i < 4; i++) {
            int ch = tid + i * 256, r = ch >> 4, c = (ch & 15) * 8;
            cpasync16(Vs0 + r*LDK + c, Vb + (size_t)r*Hh + c);
        }
        cp_commit();
        if (tid < 64) sbias[tid] = amask[b*Vn + tid] ? 0.0f : -1e30f;
    }
    __syncthreads();

    uint32_t qa[8][4];
    #pragma unroll
    for (int k = 0; k < 8; k++)
        ldsm4(qa[k][0], qa[k][1], qa[k][2], qa[k][3],
              Qs + (wm*16 + a_row) * LDK + k*16 + a_kof);

    float oacc[8][4];
    #pragma unroll
    for (int j = 0; j < 8; j++)
        #pragma unroll
        for (int e = 0; e < 4; e++) oacc[j][e] = 0.0f;
    float mrun0 = -1e30f, mrun1 = -1e30f, l0 = 0.0f, l1 = 0.0f;

    #pragma unroll 1
    for (int jt = 0; jt < Vn/64; jt++) {
        const int st = jt & 1;
        cp_wait0();
        __syncthreads();

        if (jt + 1 < Vn/64) {
            const int ns = st ^ 1;
            bf16* Ksn = KVs + ns*2*64*LDK;
            bf16* Vsn = Ksn + 64*LDK;
            const bf16* Kb = K + ((size_t)(b*Vn + (jt+1)*64)) * Hh + h*HDd;
            const bf16* Vb = V + ((size_t)(b*Vn + (jt+1)*64)) * Hh + h*HDd;
            #pragma unroll
            for (int i = 0; i < 4; i++) {
                int ch = tid + i * 256, r = ch >> 4, c = (ch & 15) * 8;
                cpasync16(Ksn + r*LDK + c, Kb + (size_t)r*Hh + c);
            }
            #pragma unroll
            for (int i = 0; i < 4; i++) {
                int ch = tid + i * 256, r = ch >> 4, c = (ch & 15) * 8;
                cpasync16(Vsn + r*LDK + c, Vb + (size_t)r*Hh + c);
            }
            cp_commit();
            if (tid < 64) sbias[(st^1)*64 + tid] =
                amask[b*Vn + (jt+1)*64 + tid] ? 0.0f : -1e30f;
        }

        const bf16* Ksb = KVs + st*2*64*LDK;
        const bf16* Vsb = Ksb + 64*LDK;

        float sacc[4][4];
        #pragma unroll
        for (int t = 0; t < 4; t++)
            #pragma unroll
            for (int e = 0; e < 4; e++) sacc[t][e] = 0.0f;
        #pragma unroll
        for (int k = 0; k < 8; k++) {
            #pragma unroll
            for (int g = 0; g < 2; g++) {
                uint32_t u0, u1, u2, u3;
                ldsm4(u0, u1, u2, u3,
                      Ksb + (wn*32 + g*16 + b_row) * LDK + k*16 + b_kof);
                uint32_t bb0[2] = {u0, u1}, bb1[2] = {u2, u3};
                mma16816(sacc[g*2  ], qa[k], bb0);
                mma16816(sacc[g*2+1], qa[k], bb1);
            }
        }

        float m0 = -1e30f, m1 = -1e30f;
        #pragma unroll
        for (int t = 0; t < 4; t++) {
            const int c0 = wn*32 + t*8 + qp*2;
            float bi0 = sbias[st*64 + c0], bi1 = sbias[st*64 + c0 + 1];
            sacc[t][0] += bi0; sacc[t][1] += bi1;
            sacc[t][2] += bi0; sacc[t][3] += bi1;
            m0 = fmaxf(m0, fmaxf(sacc[t][0], sacc[t][1]));
            m1 = fmaxf(m1, fmaxf(sacc[t][2], sacc[t][3]));
        }
        m0 = fmaxf(m0, __shfl_xor_sync(0xffffffffu, m0, 1));
        m0 = fmaxf(m0, __shfl_xor_sync(0xffffffffu, m0, 2));
        m1 = fmaxf(m1, __shfl_xor_sync(0xffffffffu, m1, 1));
        m1 = fmaxf(m1, __shfl_xor_sync(0xffffffffu, m1, 2));
        if (qp == 0) {
            pm[wn*64 + wm*16 + r0]     = m0;
            pm[wn*64 + wm*16 + r0 + 8] = m1;
        }
        __syncthreads();
        float mt0 = fmaxf(m0, pm[(wn^1)*64 + wm*16 + r0]);
        float mt1 = fmaxf(m1, pm[(wn^1)*64 + wm*16 + r0 + 8]);
        float mn0 = fmaxf(mrun0, mt0), mn1 = fmaxf(mrun1, mt1);
        float al0 = __expf(mrun0 - mn0), al1 = __expf(mrun1 - mn1);
        mrun0 = mn0; mrun1 = mn1;

        float s0 = 0.0f, s1 = 0.0f;
        #pragma unroll
        for (int t = 0; t < 4; t++) {
            float p00 = __expf(sacc[t][0] - mn0), p01 = __expf(sacc[t][1] - mn0);
            float p10 = __expf(sacc[t][2] - mn1), p11 = __expf(sacc[t][3] - mn1);
            s0 += p00 + p01; s1 += p10 + p11;
            __nv_bfloat162 w0 = __floats2bfloat162_rn(p00, p01);
            __nv_bfloat162 w1 = __floats2bfloat162_rn(p10, p11);
            const int c0 = wn*32 + t*8 + qp*2;
            *(__nv_bfloat162*)(Ps + (wm*16 + r0)     * LDP2 + c0) = w0;
            *(__nv_bfloat162*)(Ps + (wm*16 + r0 + 8) * LDP2 + c0) = w1;
        }
        s0 += __shfl_xor_sync(0xffffffffu, s0, 1);
        s0 += __shfl_xor_sync(0xffffffffu, s0, 2);
        s1 += __shfl_xor_sync(0xffffffffu, s1, 1);
        s1 += __shfl_xor_sync(0xffffffffu, s1, 2);
        if (qp == 0) {
            psum[wn*64 + wm*16 + r0]     = s0;
            psum[wn*64 + wm*16 + r0 + 8] = s1;
        }
        #pragma unroll
        for (int j = 0; j < 8; j++) {
            oacc[j][0] *= al0; oacc[j][1] *= al0;
            oacc[j][2] *= al1; oacc[j][3] *= al1;
        }
        l0 *= al0; l1 *= al1;
        __syncthreads();
        l0 += psum[wm*16 + r0]     + psum[64 + wm*16 + r0];
        l1 += psum[wm*16 + r0 + 8] + psum[64 + wm*16 + r0 + 8];

        uint32_t pa[4][4];
        #pragma unroll
        for (int kt = 0; kt < 4; kt++)
            ldsm4(pa[kt][0], pa[kt][1], pa[kt][2], pa[kt][3],
                  Ps + (wm*16 + a_row) * LDP2 + kt*16 + a_kof);
        #pragma unroll
        for (int kt = 0; kt < 4; kt++) {
            #pragma unroll
            for (int g = 0; g < 4; g++) {
                uint32_t u0, u1, u2, u3;
                ldsm4t(u0, u1, u2, u3,
                       Vsb + (kt*16 + a_row) * LDK + wn*64 + g*16 + a_kof);
                uint32_t bb0[2] = {u0, u1}, bb1[2] = {u2, u3};
                mma16816(oacc[g*2  ], pa[kt], bb0);
                mma16816(oacc[g*2+1], pa[kt], bb1);
            }
        }
    }

    const float i0 = 1.0f / l0, i1 = 1.0f / l1;
    bf16* Cb = ctx + ((size_t)(b*Lq + lt*64 + wm*16)) * Hh + h*HDd;
    #pragma unroll
    for (int j = 0; j < 8; j++) {
        const int n = wn*64 + j*8 + qp*2;
        __nv_bfloat162 w0 = __floats2bfloat162_rn(oacc[j][0]*i0, oacc[j][1]*i0);
        __nv_bfloat162 w1 = __floats2bfloat162_rn(oacc[j][2]*i1, oacc[j][3]*i1);
        *(__nv_bfloat162*)(Cb + (size_t)(r0)     * Hh + n) = w0;
        *(__nv_bfloat162*)(Cb + (size_t)(r0 + 8) * Hh + n) = w1;
    }
}

// ============================================================================
// LayerNorm over last dim (4096) per row
// ============================================================================
__global__ __launch_bounds__(256) void ln_kernel(
    const float* __restrict__ X, const float* __restrict__ g,
    const float* __restrict__ be, float* __restrict__ out)
{
    __shared__ float red[20];
    const int row = blockIdx.x, tid = threadIdx.x;
    const float* x = X + (size_t)row * Hh;
    float s = 0.0f, s2 = 0.0f;
    for (int i = tid; i < Hh; i += 256) { float v = x[i]; s += v; s2 += v*v; }
    #pragma unroll
    for (int o = 16; o; o >>= 1) {
        s  += __shfl_xor_sync(0xffffffffu, s,  o);
        s2 += __shfl_xor_sync(0xffffffffu, s2, o);
    }
    if ((tid & 31) == 0) { red[tid >> 5] = s; red[8 + (tid >> 5)] = s2; }
    __syncthreads();
    if (tid < 32) {
        float a = (tid < 8) ? red[tid] : 0.0f;
        float c = (tid < 8) ? red[8 + tid] : 0.0f;
        #pragma unroll
        for (int o = 4; o; o >>= 1) {
            a += __shfl_xor_sync(0xffffffffu, a, o);
            c += __shfl_xor_sync(0xffffffffu, c, o);
        }
        if (tid == 0) { red[16] = a; red[17] = c; }
    }
    __syncthreads();
    const float mu  = red[16] * (1.0f / Hh);
    const float var = red[17] * (1.0f / Hh) - mu*mu;
    const float inv = rsqrtf(var + 1e-5f);
    for (int i = tid; i < Hh; i += 256)
        out[(size_t)row * Hh + i] = (x[i] - mu) * inv * g[i] + be[i];
}

// ============================================================================
// host launcher
// ============================================================================
extern "C" void kernel_launch(void* const* d_in, const int* in_sizes, int n_in,
                              void* d_out, int out_size)
{
    const float* hidden = (const float*)d_in[0];
    const float* vision = (const float*)d_in[1];
    const int*   amask  = (const int*)  d_in[2];
    const float* Wq = (const float*)d_in[3];
    const float* bq = (const float*)d_in[4];
    const float* Wk = (const float*)d_in[5];
    const float* bk = (const float*)d_in[6];
    const float* Wv = (const float*)d_in[7];
    const float* bv = (const float*)d_in[8];
    const float* Wo = (const float*)d_in[9];
    const float* bo = (const float*)d_in[10];
    const float* lng = (const float*)d_in[11];
    const float* lnb = (const float*)d_in[12];
    float* out = (float*)d_out;

    bf16 *phb, *pvb, *pWq, *pWk, *pWv, *pWo, *pQ, *pK, *pV, *pCtx;
    float *pX;
    cudaGetSymbolAddress((void**)&phb, g_hb);
    cudaGetSymbolAddress((void**)&pvb, g_vb);
    cudaGetSymbolAddress((void**)&pWq, g_Wqb);
    cudaGetSymbolAddress((void**)&pWk, g_Wkb);
    cudaGetSymbolAddress((void**)&pWv, g_Wvb);
    cudaGetSymbolAddress((void**)&pWo, g_Wob);
    cudaGetSymbolAddress((void**)&pQ,  g_Qb);
    cudaGetSymbolAddress((void**)&pK,  g_Kb);
    cudaGetSymbolAddress((void**)&pV,  g_Vb);
    cudaGetSymbolAddress((void**)&pCtx, g_ctx);
    cudaGetSymbolAddress((void**)&pX,  g_X);

    cudaFuncSetAttribute(gemm_mma, cudaFuncAttributeMaxDynamicSharedMemorySize, GEMM_SMEM);
    cudaFuncSetAttribute(attn3,    cudaFuncAttributeMaxDynamicSharedMemorySize, ATTN3_SMEM);

    dim3 tb(256);
    dim3 tg(GT);
    // 1) convert only Q-GEMM deps: hidden + Wq
    {
        long long tot = A4n + W4n;                       // 6M float4, 2/thread
        f2bf2<<<(unsigned)((tot + 511) / 512), tb>>>(hidden, phb, A4n, Wq, pWq, W4n);
    }

    dim3 gbc(Hh / TBN, Mrows / TBM + CONV_ROWS);         // (32, 26): gemm + conv blocks
    dim3 gb (Hh / TBN, Mrows / TBM);                     // (32, 16): gemm only

    // 2) Q GEMM + convert(vision, Wk)
    gemm_mma<<<gbc, tg, GEMM_SMEM>>>(phb, pWq, bq, nullptr, pQ, QSCALE, 0,
                                     vision, pvb, A4n, Wk, pWk, W4n);
    // 3) K GEMM + convert(Wv)
    gemm_mma<<<gbc, tg, GEMM_SMEM>>>(pvb, pWk, bk, nullptr, pK, 1.0f, 0,
                                     Wv, pWv, W4n, nullptr, nullptr, 0);
    // 4) V GEMM + convert(Wo)
    gemm_mma<<<gbc, tg, GEMM_SMEM>>>(pvb, pWv, bv, nullptr, pV, 1.0f, 0,
                                     Wo, pWo, W4n, nullptr, nullptr, 0);
    // 5) attention
    attn3<<<dim3(Lq / 64, Bb * NHh), tb, ATTN3_SMEM>>>(pQ, pK, pV, amask, pCtx);
    // 6) O GEMM (+ residual)
    gemm_mma<<<gb, tg, GEMM_SMEM>>>(pCtx, pWo, bo, hidden, pX, 1.0f, 2,
                                    nullptr, nullptr, 0, nullptr, nullptr, 0);
    // 7) LayerNorm
    ln_kernel<<<Mrows, tb>>>(pX, lng, lnb, out);
}